// round 7
// baseline (speedup 1.0000x reference)
#include <cuda_runtime.h>
#include <math.h>
#include <stdint.h>

#define B_  4
#define S_  2048
#define D_  1024
#define H_  16
#define HD_ 64
#define MS_ (B_*S_)   // 8192

// Scratch (static device globals — no allocation)
__device__ float g_Q[(size_t)MS_ * D_];
__device__ float g_K[(size_t)MS_ * D_];
__device__ float g_V[(size_t)MS_ * D_];
__device__ float g_C[(size_t)MS_ * D_];
__device__ float g_WT[4][(size_t)D_ * D_];      // transposed + tf32-rounded weights
__device__ float2 g_ML[(size_t)B_ * H_ * S_];   // per-row (max, 1/sum)

#define GEMM_SMEM  (512 * 36 * 4)                       // 73728 B
#define SCORE_SMEM ((128*68 + 256*68 + 128*4*2) * 4)    // 108544 B

// ---------------------------------------------------------------------------
// tf32 helpers (sm_80+ ISA — compiles for plain sm_103 target)
// ---------------------------------------------------------------------------
__device__ __forceinline__ float f2tf(float f) {
    uint32_t u;
    asm("cvt.rna.tf32.f32 %0, %1;" : "=r"(u) : "f"(f));
    return __uint_as_float(u);
}

__device__ __forceinline__ void mma_tf32(float* d, const uint32_t* a, const uint32_t* b) {
    asm volatile(
        "mma.sync.aligned.m16n8k8.row.col.f32.tf32.tf32.f32 "
        "{%0,%1,%2,%3}, {%4,%5,%6,%7}, {%8,%9}, {%0,%1,%2,%3};"
        : "+f"(d[0]), "+f"(d[1]), "+f"(d[2]), "+f"(d[3])
        : "r"(a[0]), "r"(a[1]), "r"(a[2]), "r"(a[3]),
          "r"(b[0]), "r"(b[1]));
}

// ===========================================================================
// Weight transposes (all 4 in one launch) + tf32 pre-round
// ===========================================================================
__global__ __launch_bounds__(256) void transpose4(
    const float* __restrict__ W0, const float* __restrict__ W1,
    const float* __restrict__ W2, const float* __restrict__ W3,
    float* __restrict__ O0, float* __restrict__ O1,
    float* __restrict__ O2, float* __restrict__ O3)
{
    int z = blockIdx.z;
    const float* in = (z == 0) ? W0 : (z == 1) ? W1 : (z == 2) ? W2 : W3;
    float* out      = (z == 0) ? O0 : (z == 1) ? O1 : (z == 2) ? O2 : O3;

    __shared__ float t[32][33];
    int x = blockIdx.x * 32 + threadIdx.x;
    int y = blockIdx.y * 32 + threadIdx.y;
#pragma unroll
    for (int j = 0; j < 32; j += 8)
        t[threadIdx.y + j][threadIdx.x] = in[(size_t)(y + j) * D_ + x];
    __syncthreads();
    x = blockIdx.y * 32 + threadIdx.x;
    y = blockIdx.x * 32 + threadIdx.y;
#pragma unroll
    for (int j = 0; j < 32; j += 8)
        out[(size_t)(y + j) * D_ + x] = f2tf(t[threadIdx.x][threadIdx.y + j]);
}

// ===========================================================================
// 128x128xK MMA mainloop, BK=32, 2-stage SMEM ping-pong, 1 sync per chunk.
// As/Bs: 256 rows x 36 (two 128-row buffers each).
// ===========================================================================
template<bool CVTA, bool CVTB>
__device__ __forceinline__ void gemm_main(
    const float* __restrict__ A, const float* __restrict__ BT,
    int K, int lda, int ldb,
    float (*As)[36], float (*Bs)[36],
    float (&acc)[4][4][4])
{
    int tid  = threadIdx.x;
    int lane = tid & 31, warp = tid >> 5;
    int g = lane >> 2, t = lane & 3;
    int wm = warp >> 2, wn = warp & 3;

    float4 pa[4], pb[4];

    // chunk 0 -> regs -> buf0
#pragma unroll
    for (int p = 0; p < 4; p++) {
        int f4 = p * 256 + tid;
        int r = f4 >> 3, c4 = (f4 & 7) * 4;
        pa[p] = *(const float4*)(A + (size_t)r * lda + c4);
        pb[p] = *(const float4*)(BT + (size_t)r * ldb + c4);
    }
#pragma unroll
    for (int p = 0; p < 4; p++) {
        int f4 = p * 256 + tid;
        int r = f4 >> 3, c4 = (f4 & 7) * 4;
        As[r][c4 + 0] = CVTA ? f2tf(pa[p].x) : pa[p].x;
        As[r][c4 + 1] = CVTA ? f2tf(pa[p].y) : pa[p].y;
        As[r][c4 + 2] = CVTA ? f2tf(pa[p].z) : pa[p].z;
        As[r][c4 + 3] = CVTA ? f2tf(pa[p].w) : pa[p].w;
        Bs[r][c4 + 0] = CVTB ? f2tf(pb[p].x) : pb[p].x;
        Bs[r][c4 + 1] = CVTB ? f2tf(pb[p].y) : pb[p].y;
        Bs[r][c4 + 2] = CVTB ? f2tf(pb[p].z) : pb[p].z;
        Bs[r][c4 + 3] = CVTB ? f2tf(pb[p].w) : pb[p].w;
    }
    int NT = K / 32;
    if (NT > 1) {   // chunk 1 -> regs
#pragma unroll
        for (int p = 0; p < 4; p++) {
            int f4 = p * 256 + tid;
            int r = f4 >> 3, c4 = (f4 & 7) * 4;
            pa[p] = *(const float4*)(A + (size_t)r * lda + 32 + c4);
            pb[p] = *(const float4*)(BT + (size_t)r * ldb + 32 + c4);
        }
    }
    __syncthreads();

    for (int it = 0; it < NT; it++) {
        int cur = (it & 1) * 128;
        if (it + 1 < NT) {
            int nb = ((it + 1) & 1) * 128;
#pragma unroll
            for (int p = 0; p < 4; p++) {
                int f4 = p * 256 + tid;
                int r = nb + (f4 >> 3), c4 = (f4 & 7) * 4;
                As[r][c4 + 0] = CVTA ? f2tf(pa[p].x) : pa[p].x;
                As[r][c4 + 1] = CVTA ? f2tf(pa[p].y) : pa[p].y;
                As[r][c4 + 2] = CVTA ? f2tf(pa[p].z) : pa[p].z;
                As[r][c4 + 3] = CVTA ? f2tf(pa[p].w) : pa[p].w;
                Bs[r][c4 + 0] = CVTB ? f2tf(pb[p].x) : pb[p].x;
                Bs[r][c4 + 1] = CVTB ? f2tf(pb[p].y) : pb[p].y;
                Bs[r][c4 + 2] = CVTB ? f2tf(pb[p].z) : pb[p].z;
                Bs[r][c4 + 3] = CVTB ? f2tf(pb[p].w) : pb[p].w;
            }
        }
        if (it + 2 < NT) {
            int k0 = (it + 2) * 32;
#pragma unroll
            for (int p = 0; p < 4; p++) {
                int f4 = p * 256 + tid;
                int r = f4 >> 3, c4 = (f4 & 7) * 4;
                pa[p] = *(const float4*)(A + (size_t)r * lda + k0 + c4);
                pb[p] = *(const float4*)(BT + (size_t)r * ldb + k0 + c4);
            }
        }

#pragma unroll
        for (int kk = 0; kk < 32; kk += 8) {
            uint32_t af[4][4], bf[4][2];
#pragma unroll
            for (int mi = 0; mi < 4; mi++) {
                int mr = cur + wm * 64 + mi * 16 + g;
                af[mi][0] = __float_as_uint(As[mr][kk + t]);
                af[mi][1] = __float_as_uint(As[mr + 8][kk + t]);
                af[mi][2] = __float_as_uint(As[mr][kk + t + 4]);
                af[mi][3] = __float_as_uint(As[mr + 8][kk + t + 4]);
            }
#pragma unroll
            for (int ni = 0; ni < 4; ni++) {
                int nr = cur + wn * 32 + ni * 8 + g;
                bf[ni][0] = __float_as_uint(Bs[nr][kk + t]);
                bf[ni][1] = __float_as_uint(Bs[nr][kk + t + 4]);
            }
#pragma unroll
            for (int mi = 0; mi < 4; mi++)
#pragma unroll
                for (int ni = 0; ni < 4; ni++)
                    mma_tf32(acc[mi][ni], af[mi], bf[ni]);
        }
        __syncthreads();
    }
}

// ===========================================================================
// Fused Q/K/V projection GEMMs (grid.z selects tensor).
// ===========================================================================
__global__ __launch_bounds__(256) void qkv_gemm(
    const float* __restrict__ Aq, const float* __restrict__ Ak,
    const float* __restrict__ Av,
    const float* __restrict__ Wq, const float* __restrict__ Wk,
    const float* __restrict__ Wv,
    const float* __restrict__ bq, const float* __restrict__ bk,
    const float* __restrict__ bv,
    float* __restrict__ Cq, float* __restrict__ Ck, float* __restrict__ Cv)
{
    extern __shared__ float sdyn[];
    float (*As)[36] = (float(*)[36])sdyn;         // 256 rows
    float (*Bs)[36] = (float(*)[36])sdyn + 256;   // 256 rows

    int z = blockIdx.z;
    const float* A    = (z == 0) ? Aq : (z == 1) ? Ak : Av;
    const float* BT   = (z == 0) ? Wq : (z == 1) ? Wk : Wv;
    const float* bias = (z == 0) ? bq : (z == 1) ? bk : bv;
    float*       C    = (z == 0) ? Cq : (z == 1) ? Ck : Cv;

    int m0 = blockIdx.y * 128, n0 = blockIdx.x * 128;

    float acc[4][4][4];
#pragma unroll
    for (int i = 0; i < 4; i++)
#pragma unroll
        for (int j = 0; j < 4; j++)
#pragma unroll
            for (int r = 0; r < 4; r++) acc[i][j][r] = 0.f;

    gemm_main<true, false>(A + (size_t)m0 * D_, BT + (size_t)n0 * D_,
                           D_, D_, D_, As, Bs, acc);

    int lane = threadIdx.x & 31, warp = threadIdx.x >> 5;
    int g = lane >> 2, t = lane & 3;
    int wm = warp >> 2, wn = warp & 3;
#pragma unroll
    for (int mi = 0; mi < 4; mi++) {
        int row = m0 + wm * 64 + mi * 16 + g;
#pragma unroll
        for (int ni = 0; ni < 4; ni++) {
            int col = n0 + wn * 32 + ni * 8 + 2 * t;
            float2 b2 = *(const float2*)(bias + col);
            float2 o0, o1;
            o0.x = f2tf(acc[mi][ni][0] + b2.x); o0.y = f2tf(acc[mi][ni][1] + b2.y);
            o1.x = f2tf(acc[mi][ni][2] + b2.x); o1.y = f2tf(acc[mi][ni][3] + b2.y);
            *(float2*)(C + (size_t)row * D_ + col)       = o0;
            *(float2*)(C + (size_t)(row + 8) * D_ + col) = o1;
        }
    }
}

// ===========================================================================
// Output projection GEMM.
// ===========================================================================
__global__ __launch_bounds__(256) void out_gemm(
    const float* __restrict__ A, const float* __restrict__ BT,
    const float* __restrict__ bias, float* __restrict__ C)
{
    extern __shared__ float sdyn[];
    float (*As)[36] = (float(*)[36])sdyn;
    float (*Bs)[36] = (float(*)[36])sdyn + 256;

    int m0 = blockIdx.y * 128, n0 = blockIdx.x * 128;

    float acc[4][4][4];
#pragma unroll
    for (int i = 0; i < 4; i++)
#pragma unroll
        for (int j = 0; j < 4; j++)
#pragma unroll
            for (int r = 0; r < 4; r++) acc[i][j][r] = 0.f;

    gemm_main<false, false>(A + (size_t)m0 * D_, BT + (size_t)n0 * D_,
                            D_, D_, D_, As, Bs, acc);

    int lane = threadIdx.x & 31, warp = threadIdx.x >> 5;
    int g = lane >> 2, t = lane & 3;
    int wm = warp >> 2, wn = warp & 3;
#pragma unroll
    for (int mi = 0; mi < 4; mi++) {
        int row = m0 + wm * 64 + mi * 16 + g;
#pragma unroll
        for (int ni = 0; ni < 4; ni++) {
            int col = n0 + wn * 32 + ni * 8 + 2 * t;
            float2 b2 = *(const float2*)(bias + col);
            float2 o0, o1;
            o0.x = acc[mi][ni][0] + b2.x; o0.y = acc[mi][ni][1] + b2.y;
            o1.x = acc[mi][ni][2] + b2.x; o1.y = acc[mi][ni][3] + b2.y;
            *(float2*)(C + (size_t)row * D_ + col)       = o0;
            *(float2*)(C + (size_t)(row + 8) * D_ + col) = o1;
        }
    }
}

// ===========================================================================
// Scores + online softmax stats: CTA = 128 queries x all 2048 keys, one (b,h).
// K tiles double-buffered in smem (1 sync/tile). grid (16, 64).
// ===========================================================================
__global__ __launch_bounds__(256) void scores_ml(float* __restrict__ attn)
{
    extern __shared__ float sdyn[];
    float (*Qs)[68] = (float(*)[68])sdyn;                 // 128 rows
    float (*Bs)[68] = (float(*)[68])sdyn + 128;           // 256 rows (2 buf)
    float (*Ms)[4]  = (float(*)[4])(sdyn + 128*68 + 256*68);
    float (*Ls)[4]  = (float(*)[4])(sdyn + 128*68 + 256*68 + 128*4);

    int tid  = threadIdx.x;
    int lane = tid & 31, warp = tid >> 5;
    int g = lane >> 2, t = lane & 3;
    int wm = warp >> 2, wn = warp & 3;

    int bh = blockIdx.y;
    int b = bh >> 4, h = bh & 15;
    int q0 = blockIdx.x * 128;

    const float* Qb = g_Q + ((size_t)b * S_ + q0) * D_ + h * HD_;
    const float* Kb = g_K + (size_t)b * S_ * D_ + h * HD_;

    // load Q tile 128 x 64 (pre-rounded tf32 in g_Q)
#pragma unroll
    for (int p = 0; p < 8; p++) {
        int f4 = p * 256 + tid;
        int r = f4 >> 4, c4 = (f4 & 15) * 4;
        *(float4*)(&Qs[r][c4]) = *(const float4*)(Qb + (size_t)r * D_ + c4);
    }

    float m8[8], l8[8];
#pragma unroll
    for (int i = 0; i < 8; i++) { m8[i] = -3.0e38f; l8[i] = 0.f; }

    float4 pk[8];
    // K tile 0 -> regs -> buf0
#pragma unroll
    for (int p = 0; p < 8; p++) {
        int f4 = p * 256 + tid;
        int r = f4 >> 4, c4 = (f4 & 15) * 4;
        pk[p] = *(const float4*)(Kb + (size_t)r * D_ + c4);
    }
#pragma unroll
    for (int p = 0; p < 8; p++) {
        int f4 = p * 256 + tid;
        int r = f4 >> 4, c4 = (f4 & 15) * 4;
        *(float4*)(&Bs[r][c4]) = pk[p];
    }
    // K tile 1 -> regs
#pragma unroll
    for (int p = 0; p < 8; p++) {
        int f4 = p * 256 + tid;
        int r = f4 >> 4, c4 = (f4 & 15) * 4;
        pk[p] = *(const float4*)(Kb + (size_t)(128 + r) * D_ + c4);
    }
    __syncthreads();

    const float scale = 0.125f;
    size_t base = (size_t)bh * S_ * S_;

    for (int kt = 0; kt < 16; kt++) {
        int cur = (kt & 1) * 128;
        if (kt + 1 < 16) {
            int nb = ((kt + 1) & 1) * 128;
#pragma unroll
            for (int p = 0; p < 8; p++) {
                int f4 = p * 256 + tid;
                int r = nb + (f4 >> 4), c4 = (f4 & 15) * 4;
                *(float4*)(&Bs[r][c4]) = pk[p];
            }
        }
        if (kt + 2 < 16) {
            const float* Kt = Kb + (size_t)(kt + 2) * 128 * D_;
#pragma unroll
            for (int p = 0; p < 8; p++) {
                int f4 = p * 256 + tid;
                int r = f4 >> 4, c4 = (f4 & 15) * 4;
                pk[p] = *(const float4*)(Kt + (size_t)r * D_ + c4);
            }
        }

        float acc[4][4][4];
#pragma unroll
        for (int i = 0; i < 4; i++)
#pragma unroll
            for (int j = 0; j < 4; j++)
#pragma unroll
                for (int r = 0; r < 4; r++) acc[i][j][r] = 0.f;

#pragma unroll
        for (int kk = 0; kk < 64; kk += 8) {
            uint32_t af[4][4], bf[4][2];
#pragma unroll
            for (int mi = 0; mi < 4; mi++) {
                int mr = wm * 64 + mi * 16 + g;
                af[mi][0] = __float_as_uint(Qs[mr][kk + t]);
                af[mi][1] = __float_as_uint(Qs[mr + 8][kk + t]);
                af[mi][2] = __float_as_uint(Qs[mr][kk + t + 4]);
                af[mi][3] = __float_as_uint(Qs[mr + 8][kk + t + 4]);
            }
#pragma unroll
            for (int ni = 0; ni < 4; ni++) {
                int nr = cur + wn * 32 + ni * 8 + g;
                bf[ni][0] = __float_as_uint(Bs[nr][kk + t]);
                bf[ni][1] = __float_as_uint(Bs[nr][kk + t + 4]);
            }
#pragma unroll
            for (int mi = 0; mi < 4; mi++)
#pragma unroll
                for (int ni = 0; ni < 4; ni++)
                    mma_tf32(acc[mi][ni], af[mi], bf[ni]);
        }

        // scale + store raw + update online stats
#pragma unroll
        for (int mi = 0; mi < 4; mi++) {
            int row = wm * 64 + mi * 16 + g;
#pragma unroll
            for (int ni = 0; ni < 4; ni++) {
                int col = kt * 128 + wn * 32 + ni * 8 + 2 * t;
#pragma unroll
                for (int r = 0; r < 4; r++) acc[mi][ni][r] *= scale;
                float2 o0, o1;
                o0.x = acc[mi][ni][0]; o0.y = acc[mi][ni][1];
                o1.x = acc[mi][ni][2]; o1.y = acc[mi][ni][3];
                *(float2*)(attn + base + (size_t)(q0 + row) * S_ + col)     = o0;
                *(float2*)(attn + base + (size_t)(q0 + row + 8) * S_ + col) = o1;
            }
#pragma unroll
            for (int half = 0; half < 2; half++) {
                int ti = mi * 2 + half;
                float v[8];
#pragma unroll
                for (int ni = 0; ni < 4; ni++) {
                    v[ni * 2 + 0] = acc[mi][ni][half * 2 + 0];
                    v[ni * 2 + 1] = acc[mi][ni][half * 2 + 1];
                }
                float tm = v[0];
#pragma unroll
                for (int i = 1; i < 8; i++) tm = fmaxf(tm, v[i]);
                float mn = fmaxf(m8[ti], tm);
                float l = l8[ti] * __expf(m8[ti] - mn);
#pragma unroll
                for (int i = 0; i < 8; i++) l += __expf(v[i] - mn);
                m8[ti] = mn; l8[ti] = l;
            }
        }
        __syncthreads();
    }

    // reduce (m,l) over t (lanes within quad share rows)
#pragma unroll
    for (int ti = 0; ti < 8; ti++) {
        float m = m8[ti], l = l8[ti];
#pragma unroll
        for (int off = 1; off <= 2; off <<= 1) {
            float mo = __shfl_xor_sync(0xffffffffu, m, off);
            float lo = __shfl_xor_sync(0xffffffffu, l, off);
            float mn = fmaxf(m, mo);
            l = l * __expf(m - mn) + lo * __expf(mo - mn);
            m = mn;
        }
        m8[ti] = m; l8[ti] = l;
    }
    if (t == 0) {
#pragma unroll
        for (int ti = 0; ti < 8; ti++) {
            int mi = ti >> 1, half = ti & 1;
            int row = wm * 64 + mi * 16 + g + half * 8;
            Ms[row][wn] = m8[ti]; Ls[row][wn] = l8[ti];
        }
    }
    __syncthreads();
    if (tid < 128) {
        float m = Ms[tid][0], l = Ls[tid][0];
#pragma unroll
        for (int i = 1; i < 4; i++) {
            float mo = Ms[tid][i], lo = Ls[tid][i];
            float mn = fmaxf(m, mo);
            l = l * __expf(m - mn) + lo * __expf(mo - mn);
            m = mn;
        }
        g_ML[(size_t)bh * S_ + q0 + tid] = make_float2(m, 1.0f / l);
    }
}

// ===========================================================================
// Normalize + write probs + context: p = exp(s-m)*rinv; attn <- p; C = P @ V.
// 64(q) x 64(hd) tile, BK=32, smem double-buffered, 1 sync/chunk.
// grid (32, 64), 256 threads, 8 warps as 4(m) x 2(n).
// ===========================================================================
__global__ __launch_bounds__(256) void context_norm(float* __restrict__ attn)
{
    __shared__ float As[2][64][36];   // probs [q][kpos]
    __shared__ float Vs[2][64][36];   // V^T   [hd][kpos]
    __shared__ float2 MLs[64];

    int tid  = threadIdx.x;
    int lane = tid & 31, warp = tid >> 5;
    int g = lane >> 2, t = lane & 3;
    int wm = warp >> 1, wn = warp & 1;   // 4 x 2

    int bh = blockIdx.y;
    int b = bh >> 4, h = bh & 15;
    int m0 = blockIdx.x * 64;
    float* Ab = attn + (size_t)bh * S_ * S_ + (size_t)m0 * S_;
    const float* Vb = g_V + (size_t)b * S_ * D_ + h * HD_;

    if (tid < 64) MLs[tid] = g_ML[(size_t)bh * S_ + m0 + tid];

    float acc[4][4];
#pragma unroll
    for (int j = 0; j < 4; j++)
#pragma unroll
        for (int r = 0; r < 4; r++) acc[j][r] = 0.f;

    float4 pa[2], pv[2];
    // chunk 0 -> regs
#pragma unroll
    for (int p = 0; p < 2; p++) {
        int f4 = p * 256 + tid;
        int r = f4 >> 3, c4 = (f4 & 7) * 4;
        pa[p] = *(const float4*)(Ab + (size_t)r * S_ + c4);
    }
#pragma unroll
    for (int p = 0; p < 2; p++) {
        int f4 = p * 256 + tid;
        int kr = f4 >> 4, c4 = (f4 & 15) * 4;
        pv[p] = *(const float4*)(Vb + (size_t)kr * D_ + c4);
    }
    __syncthreads();   // MLs visible

    // transform + STS chunk 0 into buf0 (+ write final probs)
#pragma unroll
    for (int p = 0; p < 2; p++) {
        int f4 = p * 256 + tid;
        int r = f4 >> 3, c4 = (f4 & 7) * 4;
        float2 ml = MLs[r];
        float4 pr;
        pr.x = __expf(pa[p].x - ml.x) * ml.y;
        pr.y = __expf(pa[p].y - ml.x) * ml.y;
        pr.z = __expf(pa[p].z - ml.x) * ml.y;
        pr.w = __expf(pa[p].w - ml.x) * ml.y;
        *(float4*)(Ab + (size_t)r * S_ + c4) = pr;
        As[0][r][c4 + 0] = f2tf(pr.x); As[0][r][c4 + 1] = f2tf(pr.y);
        As[0][r][c4 + 2] = f2tf(pr.z); As[0][r][c4 + 3] = f2tf(pr.w);
    }
#pragma unroll
    for (int p = 0; p < 2; p++) {
        int f4 = p * 256 + tid;
        int kr = f4 >> 4, c4 = (f4 & 15) * 4;
        Vs[0][c4 + 0][kr] = pv[p].x; Vs[0][c4 + 1][kr] = pv[p].y;
        Vs[0][c4 + 2][kr] = pv[p].z; Vs[0][c4 + 3][kr] = pv[p].w;
    }
    // chunk 1 -> regs
#pragma unroll
    for (int p = 0; p < 2; p++) {
        int f4 = p * 256 + tid;
        int r = f4 >> 3, c4 = (f4 & 7) * 4;
        pa[p] = *(const float4*)(Ab + (size_t)r * S_ + 32 + c4);
    }
#pragma unroll
    for (int p = 0; p < 2; p++) {
        int f4 = p * 256 + tid;
        int kr = f4 >> 4, c4 = (f4 & 15) * 4;
        pv[p] = *(const float4*)(Vb + (size_t)(32 + kr) * D_ + c4);
    }
    __syncthreads();

    const int NT = S_ / 32;   // 64
    for (int it = 0; it < NT; it++) {
        int cur = it & 1;
        if (it + 1 < NT) {
            int nb = (it + 1) & 1;
            int kb = (it + 1) * 32;
#pragma unroll
            for (int p = 0; p < 2; p++) {
                int f4 = p * 256 + tid;
                int r = f4 >> 3, c4 = (f4 & 7) * 4;
                float2 ml = MLs[r];
                float4 pr;
                pr.x = __expf(pa[p].x - ml.x) * ml.y;
                pr.y = __expf(pa[p].y - ml.x) * ml.y;
                pr.z = __expf(pa[p].z - ml.x) * ml.y;
                pr.w = __expf(pa[p].w - ml.x) * ml.y;
                *(float4*)(Ab + (size_t)r * S_ + kb + c4) = pr;
                As[nb][r][c4 + 0] = f2tf(pr.x); As[nb][r][c4 + 1] = f2tf(pr.y);
                As[nb][r][c4 + 2] = f2tf(pr.z); As[nb][r][c4 + 3] = f2tf(pr.w);
            }
#pragma unroll
            for (int p = 0; p < 2; p++) {
                int f4 = p * 256 + tid;
                int kr = f4 >> 4, c4 = (f4 & 15) * 4;
                Vs[nb][c4 + 0][kr] = pv[p].x; Vs[nb][c4 + 1][kr] = pv[p].y;
                Vs[nb][c4 + 2][kr] = pv[p].z; Vs[nb][c4 + 3][kr] = pv[p].w;
            }
        }
        if (it + 2 < NT) {
            int k0 = (it + 2) * 32;
#pragma unroll
            for (int p = 0; p < 2; p++) {
                int f4 = p * 256 + tid;
                int r = f4 >> 3, c4 = (f4 & 7) * 4;
                pa[p] = *(const float4*)(Ab + (size_t)r * S_ + k0 + c4);
            }
#pragma unroll
            for (int p = 0; p < 2; p++) {
                int f4 = p * 256 + tid;
                int kr = f4 >> 4, c4 = (f4 & 15) * 4;
                pv[p] = *(const float4*)(Vb + (size_t)(k0 + kr) * D_ + c4);
            }
        }

#pragma unroll
        for (int kk = 0; kk < 32; kk += 8) {
            uint32_t af[4], bf[4][2];
            int mr = wm * 16 + g;
            af[0] = __float_as_uint(As[cur][mr][kk + t]);
            af[1] = __float_as_uint(As[cur][mr + 8][kk + t]);
            af[2] = __float_as_uint(As[cur][mr][kk + t + 4]);
            af[3] = __float_as_uint(As[cur][mr + 8][kk + t + 4]);
#pragma unroll
            for (int ni = 0; ni < 4; ni++) {
                int nr = wn * 32 + ni * 8 + g;
                bf[ni][0] = __float_as_uint(Vs[cur][nr][kk + t]);
                bf[ni][1] = __float_as_uint(Vs[cur][nr][kk + t + 4]);
            }
#pragma unroll
            for (int ni = 0; ni < 4; ni++)
                mma_tf32(acc[ni], af, bf[ni]);
        }
        __syncthreads();
    }

    float* Cb = g_C + ((size_t)b * S_ + m0) * D_ + h * HD_;
    int row = wm * 16 + g;
#pragma unroll
    for (int ni = 0; ni < 4; ni++) {
        int col = wn * 32 + ni * 8 + 2 * t;
        float2 o0, o1;
        o0.x = f2tf(acc[ni][0]); o0.y = f2tf(acc[ni][1]);
        o1.x = f2tf(acc[ni][2]); o1.y = f2tf(acc[ni][3]);
        *(float2*)(Cb + (size_t)row * D_ + col)       = o0;
        *(float2*)(Cb + (size_t)(row + 8) * D_ + col) = o1;
    }
}

// ---------------------------------------------------------------------------
extern "C" void kernel_launch(void* const* d_in, const int* in_sizes, int n_in,
                              void* d_out, int out_size)
{
    const float* q  = (const float*)d_in[0];
    const float* k  = (const float*)d_in[1];
    const float* v  = (const float*)d_in[2];
    const float* Wq = (const float*)d_in[3];
    const float* bq = (const float*)d_in[4];
    const float* Wk = (const float*)d_in[5];
    const float* bk = (const float*)d_in[6];
    const float* Wv = (const float*)d_in[7];
    const float* bv = (const float*)d_in[8];
    const float* Wo = (const float*)d_in[9];
    const float* bo = (const float*)d_in[10];

    float* out  = (float*)d_out;
    float* attn = out + (size_t)MS_ * D_;   // tuple order: (output, attention)

    float *pQ, *pK, *pV, *pC, *pWT;
    cudaGetSymbolAddress((void**)&pQ, g_Q);
    cudaGetSymbolAddress((void**)&pK, g_K);
    cudaGetSymbolAddress((void**)&pV, g_V);
    cudaGetSymbolAddress((void**)&pC, g_C);
    cudaGetSymbolAddress((void**)&pWT, g_WT);

    cudaFuncSetAttribute(qkv_gemm,
                         cudaFuncAttributeMaxDynamicSharedMemorySize, GEMM_SMEM);
    cudaFuncSetAttribute(out_gemm,
                         cudaFuncAttributeMaxDynamicSharedMemorySize, GEMM_SMEM);
    cudaFuncSetAttribute(scores_ml,
                         cudaFuncAttributeMaxDynamicSharedMemorySize, SCORE_SMEM);

    float* WTq = pWT + 0 * (size_t)D_ * D_;
    float* WTk = pWT + 1 * (size_t)D_ * D_;
    float* WTv = pWT + 2 * (size_t)D_ * D_;
    float* WTo = pWT + 3 * (size_t)D_ * D_;

    transpose4<<<dim3(32, 32, 4), dim3(32, 8)>>>(Wq, Wk, Wv, Wo,
                                                 WTq, WTk, WTv, WTo);

    qkv_gemm<<<dim3(8, 64, 3), 256, GEMM_SMEM>>>(q, k, v, WTq, WTk, WTv,
                                                 bq, bk, bv, pQ, pK, pV);

    scores_ml<<<dim3(16, 64), 256, SCORE_SMEM>>>(attn);
    context_norm<<<dim3(32, 64), 256>>>(attn);

    out_gemm<<<dim3(8, 64), 256, GEMM_SMEM>>>(pC, WTo, bo, out);
}